// round 5
// baseline (speedup 1.0000x reference)
#include <cuda_runtime.h>
#include <cstdint>

// Problem constants (from reference)
#define PCR0      (-51.2f)
#define VX        (0.05f)
#define STRIDE_F  (4.0f)
#define FW        512
#define FH        512
#define NUM_CLASSES 10
#define NUM_MAX_OBJS 500
#define BATCH     16
#define OVERLAP   (0.1f)
#define MIN_RADIUS 2
#define RMAX      16
#define EPS_F32   (1.1920929e-07f)

#define HEAT_ELEMS   ((size_t)BATCH * NUM_CLASSES * FH * FW)
#define BOXES_ELEMS  ((size_t)BATCH * NUM_MAX_OBJS * 8)
#define INDS_ELEMS   ((size_t)BATCH * NUM_MAX_OBJS)

#define TOBJ   (BATCH * NUM_MAX_OBJS)      // 8000
#define TS     64                           // tile side
#define NTX    8                            // 512/64
#define NTY    8
#define TILES_PER_PLANE (NTX * NTY)         // 64
#define NTILE  (BATCH * NUM_CLASSES * TILES_PER_PLANE)  // 10240
#define CAP    64
#define TABW   17                           // RMAX+1

// Static device scratch
__device__ int   d_cnt [NTILE];
__device__ int   d_list[NTILE * CAP];
__device__ float d_exp [TOBJ * TABW];
__device__ int4  d_meta[TOBJ];              // {cxi, cyi, r, pad}

__device__ __forceinline__ float gaussian_radius(float h, float w, float ov) {
    float b1 = h + w;
    float c1 = w * h * (1.0f - ov) / (1.0f + ov);
    float sq1 = sqrtf(fmaxf(b1 * b1 - 4.0f * c1, 0.0f));
    float r1 = (b1 + sq1) * 0.5f;

    float b2 = 2.0f * (h + w);
    float c2 = (1.0f - ov) * w * h;
    float sq2 = sqrtf(fmaxf(b2 * b2 - 16.0f * c2, 0.0f));
    float r2 = (b2 + sq2) * 0.5f;

    float a3 = 4.0f * ov;
    float b3 = -2.0f * ov * (h + w);
    float c3 = (ov - 1.0f) * w * h;
    float sq3 = sqrtf(fmaxf(b3 * b3 - 4.0f * a3 * c3, 0.0f));
    float r3 = (b3 + sq3) / (2.0f * a3);

    return fminf(fminf(r1, r2), r3);
}

// One thread per object: params, exp table (zero-padded to 17), meta,
// tile binning, and the per-object outputs.
__global__ void bin_kernel(const float* __restrict__ gt,
                           float* __restrict__ boxes,
                           float* __restrict__ inds,
                           float* __restrict__ mask)
{
    const int obj = blockIdx.x * blockDim.x + threadIdx.x;
    if (obj >= TOBJ) return;
    const int b = obj / NUM_MAX_OBJS;

    const float* g = gt + (size_t)obj * 8;
    const float x  = g[0], y  = g[1], z  = g[2];
    const float dx = g[3], dy = g[4], dz = g[5];
    const float hd = g[6];
    const int   cls = (int)(g[7] - 1.0f);

    float coord_x = (x - PCR0) / VX / STRIDE_F;
    float coord_y = (y - PCR0) / VX / STRIDE_F;
    coord_x = fminf(fmaxf(coord_x, 0.0f), (float)FW - 0.5f);
    coord_y = fminf(fmaxf(coord_y, 0.0f), (float)FH - 0.5f);
    const int cxi = (int)coord_x;
    const int cyi = (int)coord_y;

    const float dxf = dx / VX / STRIDE_F;
    const float dyf = dy / VX / STRIDE_F;

    int r = (int)gaussian_radius(dxf, dyf, OVERLAP);
    r = min(max(r, MIN_RADIUS), RMAX);

    const bool valid = (dxf > 0.0f) && (dyf > 0.0f) &&
                       (cxi >= 0) && (cxi <= FW) &&
                       (cyi >= 0) && (cyi <= FH);

    {
        const float vf = valid ? 1.0f : 0.0f;
        float* bo = boxes + (size_t)obj * 8;
        bo[0] = (coord_x - (float)cxi) * vf;
        bo[1] = (coord_y - (float)cyi) * vf;
        bo[2] = z * vf;
        bo[3] = logf(fmaxf(dx, 1e-12f)) * vf;
        bo[4] = logf(fmaxf(dy, 1e-12f)) * vf;
        bo[5] = logf(fmaxf(dz, 1e-12f)) * vf;
        bo[6] = cosf(hd) * vf;
        bo[7] = sinf(hd) * vf;
        inds[obj] = valid ? (float)(cyi * FW + cxi) : 0.0f;
        mask[obj] = vf;
    }

    if (!valid) return;

    const float sigma  = (2.0f * (float)r + 1.0f) / 6.0f;
    const float inv2s2 = 1.0f / (2.0f * sigma * sigma);
    float* tab = &d_exp[obj * TABW];
    #pragma unroll
    for (int k = 0; k < TABW; k++)
        tab[k] = (k <= r) ? expf(-(float)(k * k) * inv2s2) : 0.0f;

    d_meta[obj] = make_int4(cxi, cyi, r, 0);

    const int c = min(max(cls, 0), NUM_CLASSES - 1);
    const int ty0 = max(cyi - r, 0) >> 6;
    const int ty1 = min(cyi + r, FH - 1) >> 6;
    const int tx0 = max(cxi - r, 0) >> 6;
    const int tx1 = min(cxi + r, FW - 1) >> 6;
    const int pbase = (b * NUM_CLASSES + c) * TILES_PER_PLANE;
    for (int ty = ty0; ty <= ty1; ty++)
        for (int tx = tx0; tx <= tx1; tx++) {
            const int t = pbase + ty * NTX + tx;
            const int idx = atomicAdd(&d_cnt[t], 1);
            if (idx < CAP) d_list[t * CAP + idx] = obj;
        }
}

// One block per 64x64 tile of one (batch,class) plane. Thread = 16
// consecutive pixels of one row -> 4 float4 stores. Stores double as
// the zero-fill: every heatmap element is written exactly once.
__global__ void __launch_bounds__(256) gather_kernel(float* __restrict__ heat)
{
    __shared__ int4  smeta[CAP];
    __shared__ float stab [CAP * TABW];

    const int blk  = blockIdx.x;
    const int tile = blk & (TILES_PER_PLANE - 1);
    const int pc   = blk >> 6;                 // b*NUM_CLASSES + c
    const int tx   = tile & (NTX - 1);
    const int ty   = tile >> 3;

    const int tid = threadIdx.x;
    const int row = tid >> 2;                  // 0..63
    const int y   = (ty << 6) + row;
    const int x0  = (tx << 6) + ((tid & 3) << 4);

    const int n = min(d_cnt[blk], CAP);

    if (n > 0) {
        // stage meta
        for (int i = tid; i < n; i += 256)
            smeta[i] = d_meta[d_list[blk * CAP + i]];
        // stage exp tables
        const int tot = n * TABW;
        for (int j = tid; j < tot; j += 256) {
            const int i = j / TABW;
            const int k = j - i * TABW;
            stab[j] = d_exp[d_list[blk * CAP + i] * TABW + k];
        }
        __syncthreads();
    }

    float acc[16];
    #pragma unroll
    for (int k = 0; k < 16; k++) acc[k] = 0.0f;

    for (int i = 0; i < n; i++) {
        const int4 m  = smeta[i];              // cx, cy, r
        const int ady = abs(y - m.y);
        if (ady > m.z) continue;
        const int d0 = x0 - m.x;
        if (d0 > m.z || d0 + 15 < -m.z) continue;
        const float fi = stab[i * TABW + ady];
        #pragma unroll
        for (int k = 0; k < 16; k++) {
            const int adx = abs(d0 + k);
            if (adx <= RMAX) {
                const float v = fi * stab[i * TABW + adx];
                if (v >= EPS_F32)
                    acc[k] = fmaxf(acc[k], v);
            }
        }
    }

    float* prow = heat + ((size_t)pc * FH + y) * FW + x0;
    #pragma unroll
    for (int q = 0; q < 4; q++)
        *(float4*)(prow + q * 4) =
            make_float4(acc[q*4], acc[q*4+1], acc[q*4+2], acc[q*4+3]);
}

extern "C" void kernel_launch(void* const* d_in, const int* in_sizes, int n_in,
                              void* d_out, int out_size) {
    const float* gt = (const float*)d_in[0];
    float* out = (float*)d_out;

    float* heat  = out;
    float* boxes = out + HEAT_ELEMS;
    float* inds  = out + HEAT_ELEMS + BOXES_ELEMS;
    float* mask  = out + HEAT_ELEMS + BOXES_ELEMS + INDS_ELEMS;

    static int* cnt_ptr = nullptr;
    if (cnt_ptr == nullptr)
        cudaGetSymbolAddress((void**)&cnt_ptr, d_cnt);

    cudaMemsetAsync(cnt_ptr, 0, NTILE * sizeof(int));
    bin_kernel<<<(TOBJ + 255) / 256, 256>>>(gt, boxes, inds, mask);
    gather_kernel<<<NTILE, 256>>>(heat);
}

// round 6
// speedup vs baseline: 1.2816x; 1.2816x over previous
#include <cuda_runtime.h>
#include <cstdint>

// Problem constants (from reference)
#define PCR0      (-51.2f)
#define VX        (0.05f)
#define STRIDE_F  (4.0f)
#define FW        512
#define FH        512
#define NUM_CLASSES 10
#define NUM_MAX_OBJS 500
#define BATCH     16
#define OVERLAP   (0.1f)
#define MIN_RADIUS 2
#define RMAX      16
#define EPS_F32   (1.1920929e-07f)

#define HEAT_ELEMS   ((size_t)BATCH * NUM_CLASSES * FH * FW)   // 41,943,040
#define BOXES_ELEMS  ((size_t)BATCH * NUM_MAX_OBJS * 8)        // 64,000
#define INDS_ELEMS   ((size_t)BATCH * NUM_MAX_OBJS)            // 8,000

#define TOBJ   (BATCH * NUM_MAX_OBJS)      // 8000
#define WARPS_PER_BLOCK 8

__device__ __forceinline__ float gaussian_radius(float h, float w, float ov) {
    float b1 = h + w;
    float c1 = w * h * (1.0f - ov) / (1.0f + ov);
    float sq1 = sqrtf(fmaxf(b1 * b1 - 4.0f * c1, 0.0f));
    float r1 = (b1 + sq1) * 0.5f;

    float b2 = 2.0f * (h + w);
    float c2 = (1.0f - ov) * w * h;
    float sq2 = sqrtf(fmaxf(b2 * b2 - 16.0f * c2, 0.0f));
    float r2 = (b2 + sq2) * 0.5f;

    float a3 = 4.0f * ov;
    float b3 = -2.0f * ov * (h + w);
    float c3 = (ov - 1.0f) * w * h;
    float sq3 = sqrtf(fmaxf(b3 * b3 - 4.0f * a3 * c3, 0.0f));
    float r3 = (b3 + sq3) / (2.0f * a3);

    return fminf(fminf(r1, r2), r3);
}

// One WARP per object. Exp table lives in lane registers (lane k holds
// exp(-k^2/(2 sigma^2)) for k<=r, else 0); factors fetched via shfl.
// No shared memory, no __syncthreads.
__global__ void __launch_bounds__(32 * WARPS_PER_BLOCK) splat_kernel(
        const float* __restrict__ gt,
        float* __restrict__ heat,
        float* __restrict__ boxes,
        float* __restrict__ inds,
        float* __restrict__ mask)
{
    const int lane = threadIdx.x & 31;
    const int obj  = blockIdx.x * WARPS_PER_BLOCK + (threadIdx.x >> 5);
    const int b    = obj / NUM_MAX_OBJS;

    const float* g = gt + (size_t)obj * 8;   // broadcast loads (all lanes same addr)
    const float x  = g[0], y  = g[1], z  = g[2];
    const float dx = g[3], dy = g[4], dz = g[5];
    const float hd = g[6];
    const int   cls = (int)(g[7] - 1.0f);

    float coord_x = (x - PCR0) / VX / STRIDE_F;
    float coord_y = (y - PCR0) / VX / STRIDE_F;
    coord_x = fminf(fmaxf(coord_x, 0.0f), (float)FW - 0.5f);
    coord_y = fminf(fmaxf(coord_y, 0.0f), (float)FH - 0.5f);
    const int cxi = (int)coord_x;
    const int cyi = (int)coord_y;

    const float dxf = dx / VX / STRIDE_F;
    const float dyf = dy / VX / STRIDE_F;

    int r = (int)gaussian_radius(dxf, dyf, OVERLAP);
    r = min(max(r, MIN_RADIUS), RMAX);

    const bool valid = (dxf > 0.0f) && (dyf > 0.0f) &&
                       (cxi >= 0) && (cxi <= FW) &&
                       (cyi >= 0) && (cyi <= FH);

    // Per-object outputs (lane 0)
    if (lane == 0) {
        const float vf = valid ? 1.0f : 0.0f;
        float* bo = boxes + (size_t)obj * 8;
        bo[0] = (coord_x - (float)cxi) * vf;
        bo[1] = (coord_y - (float)cyi) * vf;
        bo[2] = z * vf;
        bo[3] = logf(fmaxf(dx, 1e-12f)) * vf;
        bo[4] = logf(fmaxf(dy, 1e-12f)) * vf;
        bo[5] = logf(fmaxf(dz, 1e-12f)) * vf;
        bo[6] = cosf(hd) * vf;
        bo[7] = sinf(hd) * vf;
        inds[obj] = valid ? (float)(cyi * FW + cxi) : 0.0f;
        mask[obj] = vf;
    }

    if (!valid) return;   // warp-uniform

    // Register-resident 1D gaussian table: one expf per warp
    const float sigma  = (2.0f * (float)r + 1.0f) / 6.0f;
    const float inv2s2 = 1.0f / (2.0f * sigma * sigma);
    const float lk     = (float)lane;
    const float tabval = (lane <= r) ? expf(-(lk * lk) * inv2s2) : 0.0f;

    // Column assignment (hoisted out of row loop). Out-of-radius lanes get
    // factor 0.0 -> skipped by the EPS guard.
    const int   oj0 = lane - r;
    const int   xx0 = cxi + oj0;
    const float fj0 = __shfl_sync(0xFFFFFFFFu, tabval, min(abs(oj0), 31));
    const bool  ok0 = ((unsigned)xx0 < FW);

    const int   oj1 = lane + 32 - r;          // only meaningful when r == 16
    const int   xx1 = cxi + oj1;
    const float fj1 = __shfl_sync(0xFFFFFFFFu, tabval, min(oj1, 31)); // oj1 >= 16 > 0
    const bool  ok1 = ((unsigned)xx1 < FW);

    const int c = min(max(cls, 0), NUM_CLASSES - 1);
    unsigned int* plane =
        (unsigned int*)(heat + ((size_t)(b * NUM_CLASSES + c) * FH) * FW);

    for (int oi = -r; oi <= r; oi++) {
        const int yy = cyi + oi;
        if ((unsigned)yy >= FH) continue;     // warp-uniform
        const float fi = __shfl_sync(0xFFFFFFFFu, tabval, abs(oi));
        unsigned int* prow = plane + (size_t)yy * FW;

        const float g0 = fi * fj0;
        if (ok0 && g0 >= EPS_F32)
            atomicMax(prow + xx0, __float_as_uint(g0));

        const float g1 = fi * fj1;
        if (ok1 && g1 >= EPS_F32)
            atomicMax(prow + xx1, __float_as_uint(g1));
    }
}

extern "C" void kernel_launch(void* const* d_in, const int* in_sizes, int n_in,
                              void* d_out, int out_size) {
    const float* gt = (const float*)d_in[0];
    float* out = (float*)d_out;

    float* heat  = out;
    float* boxes = out + HEAT_ELEMS;
    float* inds  = out + HEAT_ELEMS + BOXES_ELEMS;
    float* mask  = out + HEAT_ELEMS + BOXES_ELEMS + INDS_ELEMS;

    // Zero only the heatmap region; splat_kernel writes every
    // boxes/inds/mask slot itself (valid and invalid objects).
    cudaMemsetAsync(heat, 0, HEAT_ELEMS * sizeof(float));
    splat_kernel<<<TOBJ / WARPS_PER_BLOCK, 32 * WARPS_PER_BLOCK>>>(
        gt, heat, boxes, inds, mask);
}